// round 3
// baseline (speedup 1.0000x reference)
#include <cuda_runtime.h>

// Type-2 NUFFT, exact DFT, separable twiddle factorization.
//   y[b,c,m] = sum_iy ey[m,iy] * ( sum_ix ex[m,ix] * x[b,c,iy,ix] )
// with ey = exp(-i*t0*(iy-32)), ex = exp(-i*t1*(ix-32)).
//
// One CTA per (frame b, block of 64 samples). x[b] staged in smem
// (padded row stride -> conflict-free LDS.128 with lane==row).
// Each warp handles 4 samples; lane L owns image rows {L, L+32}.

#define NB 16
#define NC 4
#define NH 64
#define NW 64
#define NM 2048

#define TS 4                      // samples per warp
#define NWARPS 16
#define NTHREADS (NWARPS * 32)    // 512
#define SPC (NWARPS * TS)         // 64 samples per CTA
#define BLKS_PER_B (NM / SPC)     // 32

#define ROWSTRIDE 516             // floats per image row in smem (512 + 4 pad)
#define XS_FLOATS (NH * ROWSTRIDE)        // 33024
#define TAB_FLOATS (SPC * 2 * NH * 2)     // 16384  [sample][axis][i][cos,sin]
#define SMEM_BYTES ((XS_FLOATS + TAB_FLOATS) * 4)   // 197632 B

__global__ void __launch_bounds__(NTHREADS, 1)
nufft2_kernel(const float* __restrict__ xre, const float* __restrict__ xim,
              const float* __restrict__ traj, float* __restrict__ out)
{
    extern __shared__ float sm[];
    float* xs  = sm;               // [iy][ROWSTRIDE]: (ix*8 + c*2 + {re,im})
    float* tab = sm + XS_FLOATS;   // [s][axis(0=x,1=y)][i][{cos,sin}]

    const int b    = blockIdx.x / BLKS_PER_B;
    const int mblk = blockIdx.x % BLKS_PER_B;
    const int m0   = mblk * SPC;
    const int tid  = threadIdx.x;

    // ---- stage x[b] into smem ----
    const float* xrb = xre + (size_t)b * (NC * NH * NW);
    const float* xib = xim + (size_t)b * (NC * NH * NW);
    #pragma unroll 1
    for (int idx = tid; idx < NC * NH * NW; idx += NTHREADS) {
        int c   = idx >> 12;       // / 4096
        int pix = idx & 4095;
        int iy  = pix >> 6;
        int ix  = pix & 63;
        float vr = __ldg(xrb + idx);
        float vi = __ldg(xib + idx);
        float* d = xs + iy * ROWSTRIDE + ix * 8 + c * 2;
        d[0] = vr;
        d[1] = vi;
    }

    // ---- build per-sample twiddle tables (8192 sincos per CTA) ----
    // axis 0: ex uses traj[...,1] (pairs with gx); axis 1: ey uses traj[...,0]
    #pragma unroll 1
    for (int e = tid; e < SPC * 2 * NH; e += NTHREADS) {
        int s    = e >> 7;          // sample in block
        int rest = e & 127;
        int axis = rest >> 6;
        int i    = rest & 63;
        int m    = m0 + s;
        float t  = traj[((size_t)b * NM + m) * 2 + (axis ? 0 : 1)];
        float ph = -t * (float)(i - 32);
        // manual 2*pi range reduction so __sincosf stays accurate
        ph -= 6.283185307179586f * rintf(ph * 0.15915494309189535f);
        float sn, cs;
        __sincosf(ph, &sn, &cs);
        tab[2 * e + 0] = cs;
        tab[2 * e + 1] = sn;
    }
    __syncthreads();

    const int warp = tid >> 5;
    const int lane = tid & 31;
    const float* x0 = xs + lane * ROWSTRIDE;          // row = lane
    const float* x1 = xs + (lane + 32) * ROWSTRIDE;   // row = lane + 32
    const float* tb = tab + (size_t)(warp * TS) * (2 * NH * 2);  // 256 floats / sample

    // accumulators: acc[t][c][row][re/im]  (64 regs)
    float acc[TS][NC][2][2];
    #pragma unroll
    for (int t = 0; t < TS; ++t)
        #pragma unroll
        for (int c = 0; c < NC; ++c)
            #pragma unroll
            for (int r = 0; r < 2; ++r) {
                acc[t][c][r][0] = 0.0f;
                acc[t][c][r][1] = 0.0f;
            }

    // ---- stage 1: s[row] += ex[ix] (*) x[row, ix], 4 coils x 4 samples ----
    #pragma unroll 2
    for (int ix = 0; ix < NW; ++ix) {
        float2 ev[TS];
        #pragma unroll
        for (int t = 0; t < TS; ++t)
            ev[t] = *(const float2*)(tb + t * 256 + 2 * ix);   // broadcast LDS

        float4 xa = *(const float4*)(x0 + ix * 8);
        float4 xb = *(const float4*)(x0 + ix * 8 + 4);
        float4 xc = *(const float4*)(x1 + ix * 8);
        float4 xd = *(const float4*)(x1 + ix * 8 + 4);
        float xrv[2][NC] = {{xa.x, xa.z, xb.x, xb.z}, {xc.x, xc.z, xd.x, xd.z}};
        float xiv[2][NC] = {{xa.y, xa.w, xb.y, xb.w}, {xc.y, xc.w, xd.y, xd.w}};

        #pragma unroll
        for (int t = 0; t < TS; ++t) {
            float er = ev[t].x, ei = ev[t].y;
            #pragma unroll
            for (int r = 0; r < 2; ++r) {
                #pragma unroll
                for (int c = 0; c < NC; ++c) {
                    float xr = xrv[r][c], xi2 = xiv[r][c];
                    acc[t][c][r][0] = fmaf(er,  xr,  acc[t][c][r][0]);
                    acc[t][c][r][0] = fmaf(-ei, xi2, acc[t][c][r][0]);
                    acc[t][c][r][1] = fmaf(er,  xi2, acc[t][c][r][1]);
                    acc[t][c][r][1] = fmaf(ei,  xr,  acc[t][c][r][1]);
                }
            }
        }
    }

    // ---- stage 2: y = sum_iy ey[iy] (*) s[iy], warp butterfly reduce ----
    float zr[TS][NC], zi[TS][NC];
    #pragma unroll
    for (int t = 0; t < TS; ++t) {
        float2 ey0 = *(const float2*)(tb + t * 256 + 128 + 2 * lane);
        float2 ey1 = *(const float2*)(tb + t * 256 + 128 + 2 * (lane + 32));
        #pragma unroll
        for (int c = 0; c < NC; ++c) {
            float s0r = acc[t][c][0][0], s0i = acc[t][c][0][1];
            float s1r = acc[t][c][1][0], s1i = acc[t][c][1][1];
            float vr = ey0.x * s0r - ey0.y * s0i + ey1.x * s1r - ey1.y * s1i;
            float vi = ey0.x * s0i + ey0.y * s0r + ey1.x * s1i + ey1.y * s1r;
            #pragma unroll
            for (int off = 16; off > 0; off >>= 1) {
                vr += __shfl_xor_sync(0xffffffffu, vr, off);
                vi += __shfl_xor_sync(0xffffffffu, vi, off);
            }
            zr[t][c] = vr;
            zi[t][c] = vi;
        }
    }

    if (lane == 0) {
        #pragma unroll
        for (int t = 0; t < TS; ++t) {
            int m = m0 + warp * TS + t;
            #pragma unroll
            for (int c = 0; c < NC; ++c) {
                float2* o = (float2*)(out + (((size_t)b * NC + c) * NM + m) * 2);
                *o = make_float2(zr[t][c], zi[t][c]);
            }
        }
    }
}

extern "C" void kernel_launch(void* const* d_in, const int* in_sizes, int n_in,
                              void* d_out, int out_size)
{
    const float* xre  = (const float*)d_in[0];   // [B,C,H,W] f32
    const float* xim  = (const float*)d_in[1];   // [B,C,H,W] f32
    const float* traj = (const float*)d_in[2];   // [B,M,2]   f32
    float* out        = (float*)d_out;           // [B,C,M,2] f32

    cudaFuncSetAttribute(nufft2_kernel,
                         cudaFuncAttributeMaxDynamicSharedMemorySize, SMEM_BYTES);
    nufft2_kernel<<<NB * BLKS_PER_B, NTHREADS, SMEM_BYTES>>>(xre, xim, traj, out);
}